// round 1
// baseline (speedup 1.0000x reference)
#include <cuda_runtime.h>
#include <cstdint>

#define D 128
#define NVOX (D * D * D)

__global__ void __launch_bounds__(256, 8)
ca_update_kernel(const float* __restrict__ x,
                 const float* __restrict__ out,
                 float* __restrict__ y)
{
    int v = blockIdx.x * blockDim.x + threadIdx.x;
    if (v >= NVOX) return;

    int k = v & (D - 1);
    int j = (v >> 7) & (D - 1);
    int i = (v >> 14) & (D - 1);

    // out: 8 floats per voxel, 32B-aligned -> two float4 loads
    const float4* o4 = reinterpret_cast<const float4*>(out + (size_t)v * 8);
    float4 oa = o4[0];   // logits for state argmax
    float4 ob = o4[1];   // rot1 (x,y,z) + field (w)

    // argmax over 4 logits, first-occurrence on ties (strict >)
    int   state1 = 0;
    float best   = oa.x;
    if (oa.y > best) { best = oa.y; state1 = 1; }
    if (oa.z > best) { best = oa.z; state1 = 2; }
    if (oa.w > best) { best = oa.w; state1 = 3; }

    const float* xv = x + (size_t)v * 5;
    float s0f = xv[0];
    float e0  = xv[1];
    float e1  = xv[2];
    float e2  = xv[3];
    int state0 = (int)s0f;
    if (state0 == 0) state1 = 0;

    float field1 = ob.w;
    float y_e0 = e0, y_e1 = e1, y_e2 = e2;

    if (state1 <= 1) {
        field1 = -1.0f;
        y_e0 = -1.0f; y_e1 = -1.0f; y_e2 = -1.0f;
    } else if (state1 == 2) {
        field1 = fminf(fmaxf(field1, 0.0f), 0.92f);
    } else { // state1 == 3
        field1 = 1.0f;
    }

    // solidification: pick euler of neighbor minimizing ||euler_nb - rot1||^2
    bool flag = (state0 <= 1) && (state1 > 1);
    if (flag) {
        float rx = ob.x, ry = ob.y, rz = ob.z;
        float bestd = 3.4e38f;
        // lexicographic (di, dj, dk) order, skip center, strict < for
        // first-occurrence argmin (matches jnp.argmin over stacked slices)
        #pragma unroll
        for (int di = -1; di <= 1; di++) {
            #pragma unroll
            for (int dj = -1; dj <= 1; dj++) {
                #pragma unroll
                for (int dk = -1; dk <= 1; dk++) {
                    if (di == 0 && dj == 0 && dk == 0) continue;
                    int ii = i + di, jj = j + dj, kk = k + dk;
                    float n0 = 0.0f, n1 = 0.0f, n2 = 0.0f;
                    if ((unsigned)ii < (unsigned)D &&
                        (unsigned)jj < (unsigned)D &&
                        (unsigned)kk < (unsigned)D) {
                        const float* nb =
                            x + (((size_t)ii * D + jj) * D + kk) * 5 + 1;
                        n0 = nb[0];
                        n1 = nb[1];
                        n2 = nb[2];
                    }
                    float d0 = n0 - rx;
                    float d1 = n1 - ry;
                    float d2 = n2 - rz;
                    float dist = d0 * d0 + d1 * d1 + d2 * d2;
                    if (dist < bestd) {
                        bestd = dist;
                        y_e0 = n0; y_e1 = n1; y_e2 = n2;
                    }
                }
            }
        }
    }

    float* yv = y + (size_t)v * 5;
    yv[0] = (float)state1;
    yv[1] = y_e0;
    yv[2] = y_e1;
    yv[3] = y_e2;
    yv[4] = field1;
}

extern "C" void kernel_launch(void* const* d_in, const int* in_sizes, int n_in,
                              void* d_out, int out_size)
{
    const float* x   = (const float*)d_in[0];
    const float* out = (const float*)d_in[1];
    // Robustness: x has 5*D^3 elements, out has 8*D^3. Swap if order differs.
    if (n_in >= 2 && in_sizes[0] == 8 * NVOX && in_sizes[1] == 5 * NVOX) {
        const float* t = x; x = out; out = t;
    }
    float* y = (float*)d_out;

    int threads = 256;
    int blocks  = NVOX / threads;
    ca_update_kernel<<<blocks, threads>>>(x, out, y);
}